// round 16
// baseline (speedup 1.0000x reference)
#include <cuda_runtime.h>
#include <math.h>
#include <stdint.h>

// Problem constants
#define BB 2
#define SS 2048
#define HH 1024
#define NH 16
#define HD 64
#define MM (BB*SS)
#define STRIDE 45
#define SUMC 1

// Scratch (device globals: allocation-free per harness rules)
__device__ float g_q[BB*NH*SS*HD];   // [B, nh, S, hd]  (tf32-rounded)
__device__ float g_k[BB*NH*SS*HD];
__device__ float g_v[BB*NH*SS*HD];
__device__ float g_o[BB*SS*HH];      // attention out, [B, S, H] (tf32-rounded)
__device__ float g_xt[MM*HH];        // tf32-rounded inputs/weights
__device__ float g_wt[3*HH*HH];      // Wq, Wk, Wv
__device__ float g_wot[HH*HH];
// strided-head residue-pass partials (B); window pass merges inline
__device__ float g_oB[BB*8*SS*HD];
__device__ float g_mB[BB*8*SS];
__device__ float g_lB[BB*8*SS];

// ---------------------------------------------------------------------------
// helpers
// ---------------------------------------------------------------------------
__device__ __forceinline__ unsigned f2tf(float x) {
    unsigned u; asm("cvt.rna.tf32.f32 %0, %1;" : "=r"(u) : "f"(x)); return u;
}
__device__ __forceinline__ float rtf(float x) { return __uint_as_float(f2tf(x)); }
__device__ __forceinline__ void mma8(float c[4], const unsigned a[4], const unsigned b[2]) {
    asm volatile("mma.sync.aligned.m16n8k8.row.col.f32.tf32.tf32.f32 "
        "{%0,%1,%2,%3}, {%4,%5,%6,%7}, {%8,%9}, {%0,%1,%2,%3};"
        : "+f"(c[0]), "+f"(c[1]), "+f"(c[2]), "+f"(c[3])
        : "r"(a[0]), "r"(a[1]), "r"(a[2]), "r"(a[3]), "r"(b[0]), "r"(b[1]));
}
__device__ __forceinline__ void cpa16(float* s, const float* g) {
    unsigned sa = (unsigned)__cvta_generic_to_shared(s);
    asm volatile("cp.async.cg.shared.global [%0], [%1], 16;" :: "r"(sa), "l"(g));
}

// ---------------------------------------------------------------------------
// Prologue: round x / Wq / Wk / Wv / Wo to tf32 (stored as f32 bits).
// ---------------------------------------------------------------------------
#define XF4 (MM*HH/4)      // 1048576
#define WF4 (HH*HH/4)      // 262144

__global__ __launch_bounds__(256)
void precvt(const float* __restrict__ x,  const float* __restrict__ Wq,
            const float* __restrict__ Wk, const float* __restrict__ Wv,
            const float* __restrict__ Wo)
{
    int i = blockIdx.x * 256 + threadIdx.x;
    const float4* s; float4* d; int k;
    if (i < XF4) { s = (const float4*)x; d = (float4*)g_xt; k = i; }
    else {
        int w = (i - XF4) >> 18;
        k = (i - XF4) & (WF4 - 1);
        const float* srcs[4] = { Wq, Wk, Wv, Wo };
        s = (const float4*)srcs[w];
        d = (w < 3) ? (float4*)(g_wt + (size_t)w*HH*HH) : (float4*)g_wot;
    }
    float4 v = s[k];
    v.x = rtf(v.x); v.y = rtf(v.y); v.z = rtf(v.z); v.w = rtf(v.w);
    d[k] = v;
}

// ---------------------------------------------------------------------------
// GEMM (R12 config, unchanged): 128x256 tile, 256 threads, 64x64 warp tiles,
// K-tile 32, double-buffered cp.async, one barrier per k-tile.
// ---------------------------------------------------------------------------
#define RP 36
#define GEMM_SMEM2 (2*(128+256)*RP*4)   // 110592 B

template<int DO_RTF>
__device__ __forceinline__ void gemm_body(const float* __restrict__ matA,
                                          const float* __restrict__ matB,
                                          int m0, int n0,
                                          float c[4][8][4], float* sm)
{
    float* Abuf[2] = { sm,          sm + (128+256)*RP };
    float* Bbuf[2] = { sm + 128*RP, sm + (128+256)*RP + 128*RP };

    const int tid  = threadIdx.x;
#pragma unroll
    for (int i = 0; i < 12; i++) {
        int f = tid + i*256;
        if (f < 1024) {
            int r = f >> 3, c4 = (f & 7) * 4;
            cpa16(Abuf[0] + r*RP + c4, matA + (size_t)(m0+r)*HH + c4);
        } else {
            int fb = f - 1024;
            int r = fb >> 3, c4 = (fb & 7) * 4;
            cpa16(Bbuf[0] + r*RP + c4, matB + (size_t)(n0+r)*HH + c4);
        }
    }
    asm volatile("cp.async.commit_group;");

    const int warp = tid >> 5;
    const int lane = tid & 31;
    const int g = lane >> 2;
    const int t = lane & 3;
    const int wm = warp >> 2;
    const int wn = warp & 3;

    const int NT = HH / 32;
    for (int ti = 0; ti < NT; ti++) {
        asm volatile("cp.async.wait_group 0;");
        __syncthreads();
        const int cur = ti & 1;
        if (ti + 1 < NT) {
            const int k0 = (ti+1) * 32;
            const int nxt = cur ^ 1;
#pragma unroll
            for (int i = 0; i < 12; i++) {
                int f = tid + i*256;
                if (f < 1024) {
                    int r = f >> 3, c4 = (f & 7) * 4;
                    cpa16(Abuf[nxt] + r*RP + c4, matA + (size_t)(m0+r)*HH + k0 + c4);
                } else {
                    int fb = f - 1024;
                    int r = fb >> 3, c4 = (fb & 7) * 4;
                    cpa16(Bbuf[nxt] + r*RP + c4, matB + (size_t)(n0+r)*HH + k0 + c4);
                }
            }
            asm volatile("cp.async.commit_group;");
        }
        const float* As = Abuf[cur];
        const float* Bs = Bbuf[cur];
#pragma unroll
        for (int ks = 0; ks < 4; ks++) {
            const int col = ks*8 + t;
            unsigned a[4][4], b[8][2];
#pragma unroll
            for (int mf = 0; mf < 4; mf++) {
                int r = wm*64 + mf*16 + g;
                a[mf][0] = __float_as_uint(As[r*RP + col]);
                a[mf][1] = __float_as_uint(As[(r+8)*RP + col]);
                a[mf][2] = __float_as_uint(As[r*RP + col + 4]);
                a[mf][3] = __float_as_uint(As[(r+8)*RP + col + 4]);
            }
#pragma unroll
            for (int nf = 0; nf < 8; nf++) {
                int n = wn*64 + nf*8 + g;
                b[nf][0] = __float_as_uint(Bs[n*RP + col]);
                b[nf][1] = __float_as_uint(Bs[n*RP + col + 4]);
            }
#pragma unroll
            for (int mf = 0; mf < 4; mf++)
#pragma unroll
                for (int nf = 0; nf < 8; nf++)
                    mma8(c[mf][nf], a[mf], b[nf]);
        }
    }
}

__global__ __launch_bounds__(256, 1)
void qkv_mma()
{
    extern __shared__ float sm[];
    const int sel = blockIdx.x >> 2;
    const int n0 = (blockIdx.x & 3) * 256;
    const int m0 = blockIdx.y * 128;
    const float* __restrict__ W = g_wt + (size_t)sel*HH*HH;

    float c[4][8][4];
#pragma unroll
    for (int i = 0; i < 4; i++)
#pragma unroll
        for (int j = 0; j < 8; j++)
#pragma unroll
            for (int k = 0; k < 4; k++) c[i][j][k] = 0.f;

    gemm_body<1>(g_xt, W, m0, n0, c, sm);

    const int tid  = threadIdx.x;
    const int warp = tid >> 5;
    const int lane = tid & 31;
    const int g = lane >> 2;
    const int t = lane & 3;
    const int wm = warp >> 2;
    const int wn = warp & 3;

    float* dst = (sel == 0) ? g_q : (sel == 1) ? g_k : g_v;
#pragma unroll
    for (int mf = 0; mf < 4; mf++) {
#pragma unroll
        for (int half = 0; half < 2; half++) {
            int m = m0 + wm*64 + mf*16 + g + half*8;
            int bb = m >> 11, s = m & 2047;
#pragma unroll
            for (int nf = 0; nf < 8; nf++) {
                int n = n0 + wn*64 + nf*8 + 2*t;
                int h = n >> 6, d = n & 63;
                float2 v2 = half ? make_float2(c[mf][nf][2], c[mf][nf][3])
                                 : make_float2(c[mf][nf][0], c[mf][nf][1]);
                v2.x = rtf(v2.x); v2.y = rtf(v2.y);
                *(float2*)&dst[(((size_t)(bb*NH + h))*SS + s)*HD + d] = v2;
            }
        }
    }
}

__global__ __launch_bounds__(256, 1)
void oproj_mma(float* __restrict__ out)
{
    extern __shared__ float sm[];
    const int n0 = blockIdx.x * 256;
    const int m0 = blockIdx.y * 128;

    float c[4][8][4];
#pragma unroll
    for (int i = 0; i < 4; i++)
#pragma unroll
        for (int j = 0; j < 8; j++)
#pragma unroll
            for (int k = 0; k < 4; k++) c[i][j][k] = 0.f;

    gemm_body<0>(g_o, g_wot, m0, n0, c, sm);

    const int tid  = threadIdx.x;
    const int warp = tid >> 5;
    const int lane = tid & 31;
    const int g = lane >> 2;
    const int t = lane & 3;
    const int wm = warp >> 2;
    const int wn = warp & 3;

#pragma unroll
    for (int mf = 0; mf < 4; mf++) {
#pragma unroll
        for (int half = 0; half < 2; half++) {
            int m = m0 + wm*64 + mf*16 + g + half*8;
#pragma unroll
            for (int nf = 0; nf < 8; nf++) {
                int n = n0 + wn*64 + nf*8 + 2*t;
                float2 v2 = half ? make_float2(c[mf][nf][2], c[mf][nf][3])
                                 : make_float2(c[mf][nf][0], c[mf][nf][1]);
                *(float2*)&out[(size_t)m*HH + n] = v2;
            }
        }
    }
}

// ---------------------------------------------------------------------------
// Attention. Ps aliases Ks (K dead after QK^T). smem 53760 B.
// Pass 1 (attn_res): residue columns -> B partials (g_oB, g_mB, g_lB).
// Pass 2 (attn_fw): fixed heads (direct write) + window pass, which merges
// the B partials INLINE (identical combine formula to the old attn_merge,
// using register-resident A partials) and writes final g_o.
// ---------------------------------------------------------------------------
#define APAD 68
#define ATTN_SMEM_A ((3*64*APAD + 192) * 4)   // 53760 B
#define NBLK_FIXED 512
#define NBLK_WIN   512
#define NBLK_RES   720

__global__ __launch_bounds__(128)
void attn_res()
{
    extern __shared__ float sm[];
    float* Qs = sm;
    float* Ks = sm + 64*APAD;
    float* Vs = sm + 2*64*APAD;
    float* Ps = Ks;                       // alias

    const int v = blockIdx.x;
    const int r  = v % STRIDE;
    const int rest = v / STRIDE;
    const int h  = rest & 7;
    const int b  = rest >> 3;

    const float* __restrict__ qb = g_q + (size_t)(b*NH + h) * SS * HD;
    const float* __restrict__ kb = g_k + (size_t)(b*NH + h) * SS * HD;
    const float* __restrict__ vb = g_v + (size_t)(b*NH + h) * SS * HD;

    const int tid = threadIdx.x;
    const int warp = tid >> 5, lane = tid & 31;
    const int g = lane >> 2, t = lane & 3;

#pragma unroll
    for (int i = 0; i < 8; i++) {
        int f = tid + i*128;
        int p = f >> 4, c4 = (f & 15) * 4;
        int iq = r + STRIDE*p; if (iq >= SS) iq = 0;
        *(float4*)(Qs + p*APAD + c4) = *(const float4*)(qb + (size_t)iq*HD + c4);
        *(float4*)(Ks + p*APAD + c4) = *(const float4*)(kb + (size_t)iq*HD + c4);
        *(float4*)(Vs + p*APAD + c4) = *(const float4*)(vb + (size_t)iq*HD + c4);
    }
    __syncthreads();

    const int p0 = warp*16 + g;
    const int p1 = p0 + 8;
    const int i0r = r + STRIDE*p0;
    const int i1r = r + STRIDE*p1;
    const int lo0 = (i0r < SS) ? max(0, ((i0r >> 6) << 6) - 44) : 0;
    const int lo1 = (i1r < SS) ? max(0, ((i1r >> 6) << 6) - 44) : 0;

    float sc[8][4];
#pragma unroll
    for (int i = 0; i < 8; i++)
#pragma unroll
        for (int k = 0; k < 4; k++) sc[i][k] = 0.f;
#pragma unroll
    for (int ks = 0; ks < 8; ks++) {
        const int col = ks*8 + t;
        unsigned a[4];
        a[0] = __float_as_uint(Qs[p0*APAD + col]);
        a[1] = __float_as_uint(Qs[p1*APAD + col]);
        a[2] = __float_as_uint(Qs[p0*APAD + col + 4]);
        a[3] = __float_as_uint(Qs[p1*APAD + col + 4]);
#pragma unroll
        for (int nf = 0; nf < 8; nf++) {
            unsigned bf[2];
            bf[0] = __float_as_uint(Ks[(nf*8+g)*APAD + col]);
            bf[1] = __float_as_uint(Ks[(nf*8+g)*APAD + col + 4]);
            mma8(sc[nf], a, bf);
        }
    }

#pragma unroll
    for (int nf = 0; nf < 8; nf++) {
#pragma unroll
        for (int ci = 0; ci < 2; ci++) {
            int jj = nf*8 + 2*t + ci;
            int j = r + STRIDE*jj;
            sc[nf][ci]     = (j < lo0) ? sc[nf][ci]     * 0.125f : -1e30f;
            sc[nf][2 + ci] = (j < lo1) ? sc[nf][2 + ci] * 0.125f : -1e30f;
        }
    }

    float mx0 = -1e30f, mx1 = -1e30f;
#pragma unroll
    for (int nf = 0; nf < 8; nf++) {
        mx0 = fmaxf(mx0, fmaxf(sc[nf][0], sc[nf][1]));
        mx1 = fmaxf(mx1, fmaxf(sc[nf][2], sc[nf][3]));
    }
    mx0 = fmaxf(mx0, __shfl_xor_sync(0xffffffffu, mx0, 1));
    mx0 = fmaxf(mx0, __shfl_xor_sync(0xffffffffu, mx0, 2));
    mx1 = fmaxf(mx1, __shfl_xor_sync(0xffffffffu, mx1, 1));
    mx1 = fmaxf(mx1, __shfl_xor_sync(0xffffffffu, mx1, 2));
    float ps0 = 0.f, ps1 = 0.f;
#pragma unroll
    for (int nf = 0; nf < 8; nf++) {
        float p0v = (sc[nf][0] > -5e29f) ? __expf(sc[nf][0] - mx0) : 0.f; sc[nf][0] = p0v; ps0 += p0v;
        float p1v = (sc[nf][1] > -5e29f) ? __expf(sc[nf][1] - mx0) : 0.f; sc[nf][1] = p1v; ps0 += p1v;
        float p2v = (sc[nf][2] > -5e29f) ? __expf(sc[nf][2] - mx1) : 0.f; sc[nf][2] = p2v; ps1 += p2v;
        float p3v = (sc[nf][3] > -5e29f) ? __expf(sc[nf][3] - mx1) : 0.f; sc[nf][3] = p3v; ps1 += p3v;
    }
    ps0 += __shfl_xor_sync(0xffffffffu, ps0, 1);
    ps0 += __shfl_xor_sync(0xffffffffu, ps0, 2);
    ps1 += __shfl_xor_sync(0xffffffffu, ps1, 1);
    ps1 += __shfl_xor_sync(0xffffffffu, ps1, 2);

    __syncthreads();    // all warps' QK^T reads of Ks done before P store
#pragma unroll
    for (int nf = 0; nf < 8; nf++) {
        Ps[p0*APAD + nf*8 + 2*t]     = rtf(sc[nf][0]);
        Ps[p0*APAD + nf*8 + 2*t + 1] = rtf(sc[nf][1]);
        Ps[p1*APAD + nf*8 + 2*t]     = rtf(sc[nf][2]);
        Ps[p1*APAD + nf*8 + 2*t + 1] = rtf(sc[nf][3]);
    }
    __syncwarp();

    float o[8][4];
#pragma unroll
    for (int i = 0; i < 8; i++)
#pragma unroll
        for (int k = 0; k < 4; k++) o[i][k] = 0.f;
#pragma unroll
    for (int ks = 0; ks < 8; ks++) {
        const int col = ks*8 + t;
        unsigned a[4];
        a[0] = __float_as_uint(Ps[p0*APAD + col]);
        a[1] = __float_as_uint(Ps[p1*APAD + col]);
        a[2] = __float_as_uint(Ps[p0*APAD + col + 4]);
        a[3] = __float_as_uint(Ps[p1*APAD + col + 4]);
#pragma unroll
        for (int nf = 0; nf < 8; nf++) {
            unsigned bf[2];
            bf[0] = __float_as_uint(Vs[col*APAD     + nf*8 + g]);
            bf[1] = __float_as_uint(Vs[(col+4)*APAD + nf*8 + g]);
            mma8(o[nf], a, bf);
        }
    }
    __syncwarp();

    const size_t rowbase = ((size_t)(b*8 + h)) * SS;
    if (i0r < SS) {
#pragma unroll
        for (int nf = 0; nf < 8; nf++) {
            int d = nf*8 + 2*t;
            *(float2*)&g_oB[(rowbase + i0r)*HD + d] = make_float2(o[nf][0], o[nf][1]);
        }
        if (t == 0) { g_mB[rowbase + i0r] = mx0; g_lB[rowbase + i0r] = ps0; }
    }
    if (i1r < SS) {
#pragma unroll
        for (int nf = 0; nf < 8; nf++) {
            int d = nf*8 + 2*t;
            *(float2*)&g_oB[(rowbase + i1r)*HD + d] = make_float2(o[nf][2], o[nf][3]);
        }
        if (t == 0) { g_mB[rowbase + i1r] = mx1; g_lB[rowbase + i1r] = ps1; }
    }
}

// ---- window pass with INLINE merge of B partials ----
__device__ __forceinline__ void win_body(int v, float* sm)
{
    float* Qs = sm;
    float* Ks = sm + 64*APAD;
    float* Vs = sm + 2*64*APAD;
    float* Ps = Ks;                       // alias
    int* jv = (int*)(sm + 3*64*APAD);
    int* jm = jv + 64;

    const int qt = v & 31, h = (v >> 5) & 7, b = v >> 8;
    const int i0 = qt * 64;
    const int lo = (i0 >= 44) ? i0 - 44 : 0;
    const int ncols = i0 + 64 - lo;
    const int NT = (ncols + 63) >> 6;

    const float* __restrict__ qb = g_q + (size_t)(b*NH + h) * SS * HD;
    const float* __restrict__ kb = g_k + (size_t)(b*NH + h) * SS * HD;
    const float* __restrict__ vb = g_v + (size_t)(b*NH + h) * SS * HD;

    const int tid = threadIdx.x;
    const int warp = tid >> 5, lane = tid & 31;
    const int g = lane >> 2, t = lane & 3;

#pragma unroll
    for (int i = 0; i < 8; i++) {
        int f = tid + i*128;
        int r = f >> 4, c4 = (f & 15) * 4;
        *(float4*)(Qs + r*APAD + c4) = *(const float4*)(qb + (size_t)(i0+r)*HD + c4);
    }

    const int r0 = i0 + warp*16 + g;
    const int r1 = r0 + 8;
    const int im0 = r0 % STRIDE, im1 = r1 % STRIDE;

    float o[8][4];
#pragma unroll
    for (int i = 0; i < 8; i++)
#pragma unroll
        for (int k = 0; k < 4; k++) o[i][k] = 0.f;
    float m0r = -1e30f, m1r = -1e30f, l0 = 0.f, l1 = 0.f;

    for (int ti = 0; ti < NT; ti++) {
        __syncthreads();
        if (tid < 64) {
            int p = ti*64 + tid;
            int j = (p < ncols) ? (lo + p) : (1 << 28);
            jv[tid] = j;
            jm[tid] = (lo + p) % STRIDE;
        }
#pragma unroll
        for (int i = 0; i < 8; i++) {
            int f = tid + i*128;
            int r = f >> 4, c4 = (f & 15) * 4;
            int p = ti*64 + r;
            int j = (p < ncols) ? (lo + p) : lo;
            *(float4*)(Ks + r*APAD + c4) = *(const float4*)(kb + (size_t)j*HD + c4);
            *(float4*)(Vs + r*APAD + c4) = *(const float4*)(vb + (size_t)j*HD + c4);
        }
        __syncthreads();

        float sc[8][4];
#pragma unroll
        for (int i = 0; i < 8; i++)
#pragma unroll
            for (int k = 0; k < 4; k++) sc[i][k] = 0.f;
        const int qr = warp*16 + g;
#pragma unroll
        for (int ks = 0; ks < 8; ks++) {
            const int col = ks*8 + t;
            unsigned a[4];
            a[0] = __float_as_uint(Qs[qr*APAD + col]);
            a[1] = __float_as_uint(Qs[(qr+8)*APAD + col]);
            a[2] = __float_as_uint(Qs[qr*APAD + col + 4]);
            a[3] = __float_as_uint(Qs[(qr+8)*APAD + col + 4]);
#pragma unroll
            for (int nf = 0; nf < 8; nf++) {
                unsigned bf[2];
                bf[0] = __float_as_uint(Ks[(nf*8+g)*APAD + col]);
                bf[1] = __float_as_uint(Ks[(nf*8+g)*APAD + col + 4]);
                mma8(sc[nf], a, bf);
            }
        }

#pragma unroll
        for (int nf = 0; nf < 8; nf++) {
#pragma unroll
            for (int ci = 0; ci < 2; ci++) {
                int jj = nf*8 + 2*t + ci;
                int j = jv[jj];
                int jmv = jm[jj];
                bool ok0 = (j <= r0) && ((r0 - j < STRIDE) || (jmv == im0));
                bool ok1 = (j <= r1) && ((r1 - j < STRIDE) || (jmv == im1));
                sc[nf][ci]     = ok0 ? sc[nf][ci]     * 0.125f : -1e30f;
                sc[nf][2 + ci] = ok1 ? sc[nf][2 + ci] * 0.125f : -1e30f;
            }
        }

        float mx0 = -1e30f, mx1 = -1e30f;
#pragma unroll
        for (int nf = 0; nf < 8; nf++) {
            mx0 = fmaxf(mx0, fmaxf(sc[nf][0], sc[nf][1]));
            mx1 = fmaxf(mx1, fmaxf(sc[nf][2], sc[nf][3]));
        }
        mx0 = fmaxf(mx0, __shfl_xor_sync(0xffffffffu, mx0, 1));
        mx0 = fmaxf(mx0, __shfl_xor_sync(0xffffffffu, mx0, 2));
        mx1 = fmaxf(mx1, __shfl_xor_sync(0xffffffffu, mx1, 1));
        mx1 = fmaxf(mx1, __shfl_xor_sync(0xffffffffu, mx1, 2));
        float nm0 = fmaxf(m0r, mx0), nm1 = fmaxf(m1r, mx1);
        float al0 = __expf(m0r - nm0), al1 = __expf(m1r - nm1);
        float ps0 = 0.f, ps1 = 0.f;
#pragma unroll
        for (int nf = 0; nf < 8; nf++) {
            float p0 = __expf(sc[nf][0] - nm0); sc[nf][0] = p0; ps0 += p0;
            float p1 = __expf(sc[nf][1] - nm0); sc[nf][1] = p1; ps0 += p1;
            float p2 = __expf(sc[nf][2] - nm1); sc[nf][2] = p2; ps1 += p2;
            float p3 = __expf(sc[nf][3] - nm1); sc[nf][3] = p3; ps1 += p3;
        }
        ps0 += __shfl_xor_sync(0xffffffffu, ps0, 1);
        ps0 += __shfl_xor_sync(0xffffffffu, ps0, 2);
        ps1 += __shfl_xor_sync(0xffffffffu, ps1, 1);
        ps1 += __shfl_xor_sync(0xffffffffu, ps1, 2);
        m0r = nm0; m1r = nm1;
        l0 = l0*al0 + ps0;
        l1 = l1*al1 + ps1;
#pragma unroll
        for (int nf = 0; nf < 8; nf++) {
            o[nf][0] *= al0; o[nf][1] *= al0;
            o[nf][2] *= al1; o[nf][3] *= al1;
        }

        __syncthreads();
#pragma unroll
        for (int nf = 0; nf < 8; nf++) {
            Ps[qr*APAD     + nf*8 + 2*t]     = rtf(sc[nf][0]);
            Ps[qr*APAD     + nf*8 + 2*t + 1] = rtf(sc[nf][1]);
            Ps[(qr+8)*APAD + nf*8 + 2*t]     = rtf(sc[nf][2]);
            Ps[(qr+8)*APAD + nf*8 + 2*t + 1] = rtf(sc[nf][3]);
        }
        __syncwarp();

#pragma unroll
        for (int ks = 0; ks < 8; ks++) {
            const int col = ks*8 + t;
            unsigned a[4];
            a[0] = __float_as_uint(Ps[qr*APAD + col]);
            a[1] = __float_as_uint(Ps[(qr+8)*APAD + col]);
            a[2] = __float_as_uint(Ps[qr*APAD + col + 4]);
            a[3] = __float_as_uint(Ps[(qr+8)*APAD + col + 4]);
#pragma unroll
            for (int nf = 0; nf < 8; nf++) {
                unsigned bf[2];
                bf[0] = __float_as_uint(Vs[col*APAD     + nf*8 + g]);
                bf[1] = __float_as_uint(Vs[(col+4)*APAD + nf*8 + g]);
                mma8(o[nf], a, bf);
            }
        }
    }

    // INLINE merge with residue-pass B partials (same formula as old
    // attn_merge; A partials come straight from registers).
    const size_t rowbase = ((size_t)(b*8 + h)) * SS;
    {
        float mB0 = g_mB[rowbase + r0], lB0 = g_lB[rowbase + r0];
        float mB1 = g_mB[rowbase + r1], lB1 = g_lB[rowbase + r1];
        float mm0 = fmaxf(m0r, mB0), mm1 = fmaxf(m1r, mB1);
        float eA0 = __expf(m0r - mm0), eB0 = __expf(mB0 - mm0);
        float eA1 = __expf(m1r - mm1), eB1 = __expf(mB1 - mm1);
        float inv0 = 1.f / (l0*eA0 + lB0*eB0);
        float inv1 = 1.f / (l1*eA1 + lB1*eB1);
#pragma unroll
        for (int nf = 0; nf < 8; nf++) {
            int d = nf*8 + 2*t;
            float2 ob0 = *(const float2*)&g_oB[(rowbase + r0)*HD + d];
            float2 ob1 = *(const float2*)&g_oB[(rowbase + r1)*HD + d];
            *(float2*)&g_o[((size_t)b*SS + r0)*HH + h*HD + d] =
                make_float2(rtf((o[nf][0]*eA0 + ob0.x*eB0) * inv0),
                            rtf((o[nf][1]*eA0 + ob0.y*eB0) * inv0));
            *(float2*)&g_o[((size_t)b*SS + r1)*HH + h*HD + d] =
                make_float2(rtf((o[nf][2]*eA1 + ob1.x*eB1) * inv1),
                            rtf((o[nf][3]*eA1 + ob1.y*eB1) * inv1));
        }
    }
}

__device__ __forceinline__ void fixed_body(int v, float* sm)
{
    float* Qs = sm;
    float* Ks = sm + 64*APAD;
    float* Vs = sm + 2*64*APAD;
    float* Ps = Ks;                       // alias
    int* jv = (int*)(sm + 3*64*APAD);
    int* jmt = jv + 64;
    int* jdt = jmt + 64;

    const int qt = v & 31;
    const int h  = 8 + ((v >> 5) & 7);
    const int b  = v >> 8;
    const int i0 = qt * 64;

    const int nsum   = i0 / STRIDE;
    const int bstart = nsum * STRIDE;
    const int ncols  = nsum + (i0 + 64 - bstart);
    const int NT     = (ncols + 63) >> 6;

    const float* __restrict__ qb = g_q + (size_t)(b*NH + h) * SS * HD;
    const float* __restrict__ kb = g_k + (size_t)(b*NH + h) * SS * HD;
    const float* __restrict__ vb = g_v + (size_t)(b*NH + h) * SS * HD;

    const int tid = threadIdx.x;
    const int warp = tid >> 5, lane = tid & 31;
    const int g = lane >> 2, t = lane & 3;

#pragma unroll
    for (int i = 0; i < 8; i++) {
        int f = tid + i*128;
        int r = f >> 4, c4 = (f & 15) * 4;
        *(float4*)(Qs + r*APAD + c4) = *(const float4*)(qb + (size_t)(i0+r)*HD + c4);
    }

    const int r0 = i0 + warp*16 + g;
    const int r1 = r0 + 8;
    const int id0 = r0 / STRIDE, id1 = r1 / STRIDE;

    float o[8][4];
#pragma unroll
    for (int i = 0; i < 8; i++)
#pragma unroll
        for (int k = 0; k < 4; k++) o[i][k] = 0.f;
    float m0r = -1e30f, m1r = -1e30f, l0 = 0.f, l1 = 0.f;

    for (int ti = 0; ti < NT; ti++) {
        __syncthreads();
        if (tid < 64) {
            int p = ti*64 + tid;
            int j = (p < ncols) ? ((p < nsum) ? (STRIDE*p + STRIDE-1)
                                              : (bstart + p - nsum))
                                : (1 << 28);
            jv[tid] = j;
            jmt[tid] = j % STRIDE;
            jdt[tid] = j / STRIDE;
        }
#pragma unroll
        for (int i = 0; i < 8; i++) {
            int f = tid + i*128;
            int r = f >> 4, c4 = (f & 15) * 4;
            int p = ti*64 + r;
            int j = (p < ncols) ? ((p < nsum) ? (STRIDE*p + STRIDE-1)
                                              : (bstart + p - nsum)) : 0;
            *(float4*)(Ks + r*APAD + c4) = *(const float4*)(kb + (size_t)j*HD + c4);
            *(float4*)(Vs + r*APAD + c4) = *(const float4*)(vb + (size_t)j*HD + c4);
        }
        __syncthreads();

        float sc[8][4];
#pragma unroll
        for (int i = 0; i < 8; i++)
#pragma unroll
            for (int k = 0; k < 4; k++) sc[i][k] = 0.f;
        const int qr = warp*16 + g;
#pragma unroll
        for (int ks = 0; ks < 8; ks++) {
            const int col = ks*8 + t;
            unsigned a[4];
            a[0] = __float_as_uint(Qs[qr*APAD + col]);
            a[1] = __float_as_uint(Qs[(qr+8)*APAD + col]);
            a[2] = __float_as_uint(Qs[qr*APAD + col + 4]);
            a[3] = __float_as_uint(Qs[(qr+8)*APAD + col + 4]);
#pragma unroll
            for (int nf = 0; nf < 8; nf++) {
                unsigned bf[2];
                bf[0] = __float_as_uint(Ks[(nf*8+g)*APAD + col]);
                bf[1] = __float_as_uint(Ks[(nf*8+g)*APAD + col + 4]);
                mma8(sc[nf], a, bf);
            }
        }

#pragma unroll
        for (int nf = 0; nf < 8; nf++) {
#pragma unroll
            for (int ci = 0; ci < 2; ci++) {
                int jj = nf*8 + 2*t + ci;
                int j = jv[jj];
                int jmv = jmt[jj], jdv = jdt[jj];
                bool ok0 = (j <= r0) && ((jdv == id0) || (jmv >= STRIDE - SUMC));
                bool ok1 = (j <= r1) && ((jdv == id1) || (jmv >= STRIDE - SUMC));
                sc[nf][ci]     = ok0 ? sc[nf][ci]     * 0.125f : -1e30f;
                sc[nf][2 + ci] = ok1 ? sc[nf][2 + ci] * 0.125f : -1e30f;
            }
        }

        float mx0 = -1e30f, mx1 = -1e30f;
#pragma unroll
        for (int nf = 0; nf < 8; nf++) {
            mx0 = fmaxf(mx0, fmaxf(sc[nf][0], sc[nf][1]));
            mx1 = fmaxf(mx1, fmaxf(sc[nf][2], sc[nf][3]));
        }
        mx0 = fmaxf(mx0, __shfl_xor_sync(0xffffffffu, mx0, 1));
        mx0 = fmaxf(mx0, __shfl_xor_sync(0xffffffffu, mx0, 2));
        mx1 = fmaxf(mx1, __shfl_xor_sync(0xffffffffu, mx1, 1));
        mx1 = fmaxf(mx1, __shfl_xor_sync(0xffffffffu, mx1, 2));
        float nm0 = fmaxf(m0r, mx0), nm1 = fmaxf(m1r, mx1);
        float al0 = __expf(m0r - nm0), al1 = __expf(m1r - nm1);
        float ps0 = 0.f, ps1 = 0.f;
#pragma unroll
        for (int nf = 0; nf < 8; nf++) {
            float p0 = __expf(sc[nf][0] - nm0); sc[nf][0] = p0; ps0 += p0;
            float p1 = __expf(sc[nf][1] - nm0); sc[nf][1] = p1; ps0 += p1;
            float p2 = __expf(sc[nf][2] - nm1); sc[nf][2] = p2; ps1 += p2;
            float p3 = __expf(sc[nf][3] - nm1); sc[nf][3] = p3; ps1 += p3;
        }
        ps0 += __shfl_xor_sync(0xffffffffu, ps0, 1);
        ps0 += __shfl_xor_sync(0xffffffffu, ps0, 2);
        ps1 += __shfl_xor_sync(0xffffffffu, ps1, 1);
        ps1 += __shfl_xor_sync(0xffffffffu, ps1, 2);
        m0r = nm0; m1r = nm1;
        l0 = l0*al0 + ps0;
        l1 = l1*al1 + ps1;
#pragma unroll
        for (int nf = 0; nf < 8; nf++) {
            o[nf][0] *= al0; o[nf][1] *= al0;
            o[nf][2] *= al1; o[nf][3] *= al1;
        }

        __syncthreads();
#pragma unroll
        for (int nf = 0; nf < 8; nf++) {
            Ps[qr*APAD     + nf*8 + 2*t]     = rtf(sc[nf][0]);
            Ps[qr*APAD     + nf*8 + 2*t + 1] = rtf(sc[nf][1]);
            Ps[(qr+8)*APAD + nf*8 + 2*t]     = rtf(sc[nf][2]);
            Ps[(qr+8)*APAD + nf*8 + 2*t + 1] = rtf(sc[nf][3]);
        }
        __syncwarp();

#pragma unroll
        for (int ks = 0; ks < 8; ks++) {
            const int col = ks*8 + t;
            unsigned a[4];
            a[0] = __float_as_uint(Ps[qr*APAD + col]);
            a[1] = __float_as_uint(Ps[(qr+8)*APAD + col]);
            a[2] = __float_as_uint(Ps[qr*APAD + col + 4]);
            a[3] = __float_as_uint(Ps[(qr+8)*APAD + col + 4]);
#pragma unroll
            for (int nf = 0; nf < 8; nf++) {
                unsigned bf[2];
                bf[0] = __float_as_uint(Vs[col*APAD     + nf*8 + g]);
                bf[1] = __float_as_uint(Vs[(col+4)*APAD + nf*8 + g]);
                mma8(o[nf], a, bf);
            }
        }
    }

    const float inv0 = 1.f / l0, inv1 = 1.f / l1;
#pragma unroll
    for (int nf = 0; nf < 8; nf++) {
        int d = h*HD + nf*8 + 2*t;
        *(float2*)&g_o[((size_t)b*SS + r0)*HH + d] =
            make_float2(rtf(o[nf][0]*inv0), rtf(o[nf][1]*inv0));
        *(float2*)&g_o[((size_t)b*SS + r1)*HH + d] =
            make_float2(rtf(o[nf][2]*inv1), rtf(o[nf][3]*inv1));
    }
}

__global__ __launch_bounds__(128)
void attn_fw()
{
    extern __shared__ float sm[];
    int bid = blockIdx.x;
    if (bid < NBLK_FIXED) fixed_body(bid, sm);
    else                  win_body(bid - NBLK_FIXED, sm);
}

// ---------------------------------------------------------------------------
extern "C" void kernel_launch(void* const* d_in, const int* in_sizes, int n_in,
                              void* d_out, int out_size)
{
    const float* x  = (const float*)d_in[0];
    const float* Wq = (const float*)d_in[1];
    const float* Wk = (const float*)d_in[2];
    const float* Wv = (const float*)d_in[3];
    const float* Wo = (const float*)d_in[4];
    float* out = (float*)d_out;

    cudaFuncSetAttribute(qkv_mma,   cudaFuncAttributeMaxDynamicSharedMemorySize, GEMM_SMEM2);
    cudaFuncSetAttribute(oproj_mma, cudaFuncAttributeMaxDynamicSharedMemorySize, GEMM_SMEM2);
    cudaFuncSetAttribute(attn_res,  cudaFuncAttributeMaxDynamicSharedMemorySize, ATTN_SMEM_A);
    cudaFuncSetAttribute(attn_fw,   cudaFuncAttributeMaxDynamicSharedMemorySize, ATTN_SMEM_A);

    precvt<<<(XF4 + 4*WF4 + 255)/256, 256>>>(x, Wq, Wk, Wv, Wo);
    qkv_mma<<<dim3(12, 32), 256, GEMM_SMEM2>>>();
    attn_res<<<NBLK_RES, 128, ATTN_SMEM_A>>>();
    attn_fw<<<NBLK_FIXED + NBLK_WIN, 128, ATTN_SMEM_A>>>();
    oproj_mma<<<dim3(4, 32), 256, GEMM_SMEM2>>>(out);
}

// round 17
// speedup vs baseline: 1.0189x; 1.0189x over previous
#include <cuda_runtime.h>
#include <math.h>
#include <stdint.h>

// Problem constants
#define BB 2
#define SS 2048
#define HH 1024
#define NH 16
#define HD 64
#define MM (BB*SS)
#define STRIDE 45
#define SUMC 1

// Scratch (device globals: allocation-free per harness rules)
__device__ float g_q[BB*NH*SS*HD];   // [B, nh, S, hd]  (tf32-rounded)
__device__ float g_k[BB*NH*SS*HD];
__device__ float g_v[BB*NH*SS*HD];
__device__ float g_o[BB*SS*HH];      // attention out, [B, S, H] (tf32-rounded)
__device__ float g_xt[MM*HH];        // tf32-rounded inputs/weights
__device__ float g_wt[3*HH*HH];      // Wq, Wk, Wv
__device__ float g_wot[HH*HH];
// strided-head split-softmax partials
__device__ float g_oA[BB*8*SS*HD];
__device__ float g_oB[BB*8*SS*HD];
__device__ float g_mA[BB*8*SS];
__device__ float g_lA[BB*8*SS];
__device__ float g_mB[BB*8*SS];
__device__ float g_lB[BB*8*SS];

// ---------------------------------------------------------------------------
// helpers
// ---------------------------------------------------------------------------
__device__ __forceinline__ unsigned f2tf(float x) {
    unsigned u; asm("cvt.rna.tf32.f32 %0, %1;" : "=r"(u) : "f"(x)); return u;
}
__device__ __forceinline__ float rtf(float x) { return __uint_as_float(f2tf(x)); }
__device__ __forceinline__ void mma8(float c[4], const unsigned a[4], const unsigned b[2]) {
    asm volatile("mma.sync.aligned.m16n8k8.row.col.f32.tf32.tf32.f32 "
        "{%0,%1,%2,%3}, {%4,%5,%6,%7}, {%8,%9}, {%0,%1,%2,%3};"
        : "+f"(c[0]), "+f"(c[1]), "+f"(c[2]), "+f"(c[3])
        : "r"(a[0]), "r"(a[1]), "r"(a[2]), "r"(a[3]), "r"(b[0]), "r"(b[1]));
}
__device__ __forceinline__ void cpa16(float* s, const float* g) {
    unsigned sa = (unsigned)__cvta_generic_to_shared(s);
    asm volatile("cp.async.cg.shared.global [%0], [%1], 16;" :: "r"(sa), "l"(g));
}

// ---------------------------------------------------------------------------
// Prologue: round x / Wq / Wk / Wv / Wo to tf32 (stored as f32 bits).
// ---------------------------------------------------------------------------
#define XF4 (MM*HH/4)      // 1048576
#define WF4 (HH*HH/4)      // 262144

__global__ __launch_bounds__(256)
void precvt(const float* __restrict__ x,  const float* __restrict__ Wq,
            const float* __restrict__ Wk, const float* __restrict__ Wv,
            const float* __restrict__ Wo)
{
    int i = blockIdx.x * 256 + threadIdx.x;
    const float4* s; float4* d; int k;
    if (i < XF4) { s = (const float4*)x; d = (float4*)g_xt; k = i; }
    else {
        int w = (i - XF4) >> 18;
        k = (i - XF4) & (WF4 - 1);
        const float* srcs[4] = { Wq, Wk, Wv, Wo };
        s = (const float4*)srcs[w];
        d = (w < 3) ? (float4*)(g_wt + (size_t)w*HH*HH) : (float4*)g_wot;
    }
    float4 v = s[k];
    v.x = rtf(v.x); v.y = rtf(v.y); v.z = rtf(v.z); v.w = rtf(v.w);
    d[k] = v;
}

// ---------------------------------------------------------------------------
// GEMM (R12 config): 128x256 tile, 256 threads, 64x64 warp tiles,
// K-tile 32, double-buffered cp.async, one barrier per k-tile.
// ---------------------------------------------------------------------------
#define RP 36
#define GEMM_SMEM2 (2*(128+256)*RP*4)   // 110592 B

template<int DO_RTF>
__device__ __forceinline__ void gemm_body(const float* __restrict__ matA,
                                          const float* __restrict__ matB,
                                          int m0, int n0,
                                          float c[4][8][4], float* sm)
{
    float* Abuf[2] = { sm,          sm + (128+256)*RP };
    float* Bbuf[2] = { sm + 128*RP, sm + (128+256)*RP + 128*RP };

    const int tid  = threadIdx.x;
#pragma unroll
    for (int i = 0; i < 12; i++) {
        int f = tid + i*256;
        if (f < 1024) {
            int r = f >> 3, c4 = (f & 7) * 4;
            cpa16(Abuf[0] + r*RP + c4, matA + (size_t)(m0+r)*HH + c4);
        } else {
            int fb = f - 1024;
            int r = fb >> 3, c4 = (fb & 7) * 4;
            cpa16(Bbuf[0] + r*RP + c4, matB + (size_t)(n0+r)*HH + c4);
        }
    }
    asm volatile("cp.async.commit_group;");

    const int warp = tid >> 5;
    const int lane = tid & 31;
    const int g = lane >> 2;
    const int t = lane & 3;
    const int wm = warp >> 2;
    const int wn = warp & 3;

    const int NT = HH / 32;
    for (int ti = 0; ti < NT; ti++) {
        asm volatile("cp.async.wait_group 0;");
        __syncthreads();
        const int cur = ti & 1;
        if (ti + 1 < NT) {
            const int k0 = (ti+1) * 32;
            const int nxt = cur ^ 1;
#pragma unroll
            for (int i = 0; i < 12; i++) {
                int f = tid + i*256;
                if (f < 1024) {
                    int r = f >> 3, c4 = (f & 7) * 4;
                    cpa16(Abuf[nxt] + r*RP + c4, matA + (size_t)(m0+r)*HH + k0 + c4);
                } else {
                    int fb = f - 1024;
                    int r = fb >> 3, c4 = (fb & 7) * 4;
                    cpa16(Bbuf[nxt] + r*RP + c4, matB + (size_t)(n0+r)*HH + k0 + c4);
                }
            }
            asm volatile("cp.async.commit_group;");
        }
        const float* As = Abuf[cur];
        const float* Bs = Bbuf[cur];
#pragma unroll
        for (int ks = 0; ks < 4; ks++) {
            const int col = ks*8 + t;
            unsigned a[4][4], b[8][2];
#pragma unroll
            for (int mf = 0; mf < 4; mf++) {
                int r = wm*64 + mf*16 + g;
                a[mf][0] = __float_as_uint(As[r*RP + col]);
                a[mf][1] = __float_as_uint(As[(r+8)*RP + col]);
                a[mf][2] = __float_as_uint(As[r*RP + col + 4]);
                a[mf][3] = __float_as_uint(As[(r+8)*RP + col + 4]);
            }
#pragma unroll
            for (int nf = 0; nf < 8; nf++) {
                int n = wn*64 + nf*8 + g;
                b[nf][0] = __float_as_uint(Bs[n*RP + col]);
                b[nf][1] = __float_as_uint(Bs[n*RP + col + 4]);
            }
#pragma unroll
            for (int mf = 0; mf < 4; mf++)
#pragma unroll
                for (int nf = 0; nf < 8; nf++)
                    mma8(c[mf][nf], a[mf], b[nf]);
        }
    }
}

__global__ __launch_bounds__(256, 1)
void qkv_mma()
{
    extern __shared__ float sm[];
    const int sel = blockIdx.x >> 2;
    const int n0 = (blockIdx.x & 3) * 256;
    const int m0 = blockIdx.y * 128;
    const float* __restrict__ W = g_wt + (size_t)sel*HH*HH;

    float c[4][8][4];
#pragma unroll
    for (int i = 0; i < 4; i++)
#pragma unroll
        for (int j = 0; j < 8; j++)
#pragma unroll
            for (int k = 0; k < 4; k++) c[i][j][k] = 0.f;

    gemm_body<1>(g_xt, W, m0, n0, c, sm);

    const int tid  = threadIdx.x;
    const int warp = tid >> 5;
    const int lane = tid & 31;
    const int g = lane >> 2;
    const int t = lane & 3;
    const int wm = warp >> 2;
    const int wn = warp & 3;

    float* dst = (sel == 0) ? g_q : (sel == 1) ? g_k : g_v;
#pragma unroll
    for (int mf = 0; mf < 4; mf++) {
#pragma unroll
        for (int half = 0; half < 2; half++) {
            int m = m0 + wm*64 + mf*16 + g + half*8;
            int bb = m >> 11, s = m & 2047;
#pragma unroll
            for (int nf = 0; nf < 8; nf++) {
                int n = n0 + wn*64 + nf*8 + 2*t;
                int h = n >> 6, d = n & 63;
                float2 v2 = half ? make_float2(c[mf][nf][2], c[mf][nf][3])
                                 : make_float2(c[mf][nf][0], c[mf][nf][1]);
                v2.x = rtf(v2.x); v2.y = rtf(v2.y);
                *(float2*)&dst[(((size_t)(bb*NH + h))*SS + s)*HD + d] = v2;
            }
        }
    }
}

__global__ __launch_bounds__(256, 1)
void oproj_mma(float* __restrict__ out)
{
    extern __shared__ float sm[];
    const int n0 = blockIdx.x * 256;
    const int m0 = blockIdx.y * 128;

    float c[4][8][4];
#pragma unroll
    for (int i = 0; i < 4; i++)
#pragma unroll
        for (int j = 0; j < 8; j++)
#pragma unroll
            for (int k = 0; k < 4; k++) c[i][j][k] = 0.f;

    gemm_body<0>(g_o, g_wot, m0, n0, c, sm);

    const int tid  = threadIdx.x;
    const int warp = tid >> 5;
    const int lane = tid & 31;
    const int g = lane >> 2;
    const int t = lane & 3;
    const int wm = warp >> 2;
    const int wn = warp & 3;

#pragma unroll
    for (int mf = 0; mf < 4; mf++) {
#pragma unroll
        for (int half = 0; half < 2; half++) {
            int m = m0 + wm*64 + mf*16 + g + half*8;
#pragma unroll
            for (int nf = 0; nf < 8; nf++) {
                int n = n0 + wn*64 + nf*8 + 2*t;
                float2 v2 = half ? make_float2(c[mf][nf][2], c[mf][nf][3])
                                 : make_float2(c[mf][nf][0], c[mf][nf][1]);
                *(float2*)&out[(size_t)m*HH + n] = v2;
            }
        }
    }
}

// ---------------------------------------------------------------------------
// Fused attention kernel (R14 config) — Ps ALIASES Ks. smem 53760 B.
// ---------------------------------------------------------------------------
#define APAD 68
#define ATTN_SMEM_A ((3*64*APAD + 192) * 4)   // 53760 B
#define NBLK_FIXED 512
#define NBLK_WIN   512
#define NBLK_RES   720

__device__ __forceinline__ void win_body(int v, float* sm)
{
    float* Qs = sm;
    float* Ks = sm + 64*APAD;
    float* Vs = sm + 2*64*APAD;
    float* Ps = Ks;                       // alias: K dead after QK^T
    int* jv = (int*)(sm + 3*64*APAD);
    int* jm = jv + 64;

    const int qt = v & 31, h = (v >> 5) & 7, b = v >> 8;
    const int i0 = qt * 64;
    const int lo = (i0 >= 44) ? i0 - 44 : 0;
    const int ncols = i0 + 64 - lo;
    const int NT = (ncols + 63) >> 6;

    const float* __restrict__ qb = g_q + (size_t)(b*NH + h) * SS * HD;
    const float* __restrict__ kb = g_k + (size_t)(b*NH + h) * SS * HD;
    const float* __restrict__ vb = g_v + (size_t)(b*NH + h) * SS * HD;

    const int tid = threadIdx.x;
    const int warp = tid >> 5, lane = tid & 31;
    const int g = lane >> 2, t = lane & 3;

#pragma unroll
    for (int i = 0; i < 8; i++) {
        int f = tid + i*128;
        int r = f >> 4, c4 = (f & 15) * 4;
        *(float4*)(Qs + r*APAD + c4) = *(const float4*)(qb + (size_t)(i0+r)*HD + c4);
    }

    const int r0 = i0 + warp*16 + g;
    const int r1 = r0 + 8;
    const int im0 = r0 % STRIDE, im1 = r1 % STRIDE;

    float o[8][4];
#pragma unroll
    for (int i = 0; i < 8; i++)
#pragma unroll
        for (int k = 0; k < 4; k++) o[i][k] = 0.f;
    float m0r = -1e30f, m1r = -1e30f, l0 = 0.f, l1 = 0.f;

    for (int ti = 0; ti < NT; ti++) {
        __syncthreads();    // P.V reads of prior tile done before K overwrite
        if (tid < 64) {
            int p = ti*64 + tid;
            int j = (p < ncols) ? (lo + p) : (1 << 28);
            jv[tid] = j;
            jm[tid] = (lo + p) % STRIDE;
        }
#pragma unroll
        for (int i = 0; i < 8; i++) {
            int f = tid + i*128;
            int r = f >> 4, c4 = (f & 15) * 4;
            int p = ti*64 + r;
            int j = (p < ncols) ? (lo + p) : lo;
            *(float4*)(Ks + r*APAD + c4) = *(const float4*)(kb + (size_t)j*HD + c4);
            *(float4*)(Vs + r*APAD + c4) = *(const float4*)(vb + (size_t)j*HD + c4);
        }
        __syncthreads();

        float sc[8][4];
#pragma unroll
        for (int i = 0; i < 8; i++)
#pragma unroll
            for (int k = 0; k < 4; k++) sc[i][k] = 0.f;
        const int qr = warp*16 + g;
#pragma unroll
        for (int ks = 0; ks < 8; ks++) {
            const int col = ks*8 + t;
            unsigned a[4];
            a[0] = __float_as_uint(Qs[qr*APAD + col]);
            a[1] = __float_as_uint(Qs[(qr+8)*APAD + col]);
            a[2] = __float_as_uint(Qs[qr*APAD + col + 4]);
            a[3] = __float_as_uint(Qs[(qr+8)*APAD + col + 4]);
#pragma unroll
            for (int nf = 0; nf < 8; nf++) {
                unsigned bf[2];
                bf[0] = __float_as_uint(Ks[(nf*8+g)*APAD + col]);
                bf[1] = __float_as_uint(Ks[(nf*8+g)*APAD + col + 4]);
                mma8(sc[nf], a, bf);
            }
        }

#pragma unroll
        for (int nf = 0; nf < 8; nf++) {
#pragma unroll
            for (int ci = 0; ci < 2; ci++) {
                int jj = nf*8 + 2*t + ci;
                int j = jv[jj];
                int jmv = jm[jj];
                bool ok0 = (j <= r0) && ((r0 - j < STRIDE) || (jmv == im0));
                bool ok1 = (j <= r1) && ((r1 - j < STRIDE) || (jmv == im1));
                sc[nf][ci]     = ok0 ? sc[nf][ci]     * 0.125f : -1e30f;
                sc[nf][2 + ci] = ok1 ? sc[nf][2 + ci] * 0.125f : -1e30f;
            }
        }

        float mx0 = -1e30f, mx1 = -1e30f;
#pragma unroll
        for (int nf = 0; nf < 8; nf++) {
            mx0 = fmaxf(mx0, fmaxf(sc[nf][0], sc[nf][1]));
            mx1 = fmaxf(mx1, fmaxf(sc[nf][2], sc[nf][3]));
        }
        mx0 = fmaxf(mx0, __shfl_xor_sync(0xffffffffu, mx0, 1));
        mx0 = fmaxf(mx0, __shfl_xor_sync(0xffffffffu, mx0, 2));
        mx1 = fmaxf(mx1, __shfl_xor_sync(0xffffffffu, mx1, 1));
        mx1 = fmaxf(mx1, __shfl_xor_sync(0xffffffffu, mx1, 2));
        float nm0 = fmaxf(m0r, mx0), nm1 = fmaxf(m1r, mx1);
        float al0 = __expf(m0r - nm0), al1 = __expf(m1r - nm1);
        float ps0 = 0.f, ps1 = 0.f;
#pragma unroll
        for (int nf = 0; nf < 8; nf++) {
            float p0 = __expf(sc[nf][0] - nm0); sc[nf][0] = p0; ps0 += p0;
            float p1 = __expf(sc[nf][1] - nm0); sc[nf][1] = p1; ps0 += p1;
            float p2 = __expf(sc[nf][2] - nm1); sc[nf][2] = p2; ps1 += p2;
            float p3 = __expf(sc[nf][3] - nm1); sc[nf][3] = p3; ps1 += p3;
        }
        ps0 += __shfl_xor_sync(0xffffffffu, ps0, 1);
        ps0 += __shfl_xor_sync(0xffffffffu, ps0, 2);
        ps1 += __shfl_xor_sync(0xffffffffu, ps1, 1);
        ps1 += __shfl_xor_sync(0xffffffffu, ps1, 2);
        m0r = nm0; m1r = nm1;
        l0 = l0*al0 + ps0;
        l1 = l1*al1 + ps1;
#pragma unroll
        for (int nf = 0; nf < 8; nf++) {
            o[nf][0] *= al0; o[nf][1] *= al0;
            o[nf][2] *= al1; o[nf][3] *= al1;
        }

        __syncthreads();    // ALL warps' QK^T reads of Ks done before P store
#pragma unroll
        for (int nf = 0; nf < 8; nf++) {
            Ps[qr*APAD     + nf*8 + 2*t]     = rtf(sc[nf][0]);
            Ps[qr*APAD     + nf*8 + 2*t + 1] = rtf(sc[nf][1]);
            Ps[(qr+8)*APAD + nf*8 + 2*t]     = rtf(sc[nf][2]);
            Ps[(qr+8)*APAD + nf*8 + 2*t + 1] = rtf(sc[nf][3]);
        }
        __syncwarp();       // P rows are warp-private

#pragma unroll
        for (int ks = 0; ks < 8; ks++) {
            const int col = ks*8 + t;
            unsigned a[4];
            a[0] = __float_as_uint(Ps[qr*APAD + col]);
            a[1] = __float_as_uint(Ps[(qr+8)*APAD + col]);
            a[2] = __float_as_uint(Ps[qr*APAD + col + 4]);
            a[3] = __float_as_uint(Ps[(qr+8)*APAD + col + 4]);
#pragma unroll
            for (int nf = 0; nf < 8; nf++) {
                unsigned bf[2];
                bf[0] = __float_as_uint(Vs[col*APAD     + nf*8 + g]);
                bf[1] = __float_as_uint(Vs[(col+4)*APAD + nf*8 + g]);
                mma8(o[nf], a, bf);
            }
        }
    }

    const size_t rowbase = ((size_t)(b*8 + h)) * SS;
#pragma unroll
    for (int nf = 0; nf < 8; nf++) {
        int d = nf*8 + 2*t;
        *(float2*)&g_oA[(rowbase + r0)*HD + d] = make_float2(o[nf][0], o[nf][1]);
        *(float2*)&g_oA[(rowbase + r1)*HD + d] = make_float2(o[nf][2], o[nf][3]);
    }
    if (t == 0) {
        g_mA[rowbase + r0] = m0r; g_lA[rowbase + r0] = l0;
        g_mA[rowbase + r1] = m1r; g_lA[rowbase + r1] = l1;
    }
}

__device__ __forceinline__ void res_body(int v, float* sm)
{
    float* Qs = sm;
    float* Ks = sm + 64*APAD;
    float* Vs = sm + 2*64*APAD;
    float* Ps = Ks;                       // alias

    const int r  = v % STRIDE;
    const int rest = v / STRIDE;
    const int h  = rest & 7;
    const int b  = rest >> 3;

    const float* __restrict__ qb = g_q + (size_t)(b*NH + h) * SS * HD;
    const float* __restrict__ kb = g_k + (size_t)(b*NH + h) * SS * HD;
    const float* __restrict__ vb = g_v + (size_t)(b*NH + h) * SS * HD;

    const int tid = threadIdx.x;
    const int warp = tid >> 5, lane = tid & 31;
    const int g = lane >> 2, t = lane & 3;

#pragma unroll
    for (int i = 0; i < 8; i++) {
        int f = tid + i*128;
        int p = f >> 4, c4 = (f & 15) * 4;
        int iq = r + STRIDE*p; if (iq >= SS) iq = 0;
        *(float4*)(Qs + p*APAD + c4) = *(const float4*)(qb + (size_t)iq*HD + c4);
        *(float4*)(Ks + p*APAD + c4) = *(const float4*)(kb + (size_t)iq*HD + c4);
        *(float4*)(Vs + p*APAD + c4) = *(const float4*)(vb + (size_t)iq*HD + c4);
    }
    __syncthreads();

    const int p0 = warp*16 + g;
    const int p1 = p0 + 8;
    const int i0r = r + STRIDE*p0;
    const int i1r = r + STRIDE*p1;
    const int lo0 = (i0r < SS) ? max(0, ((i0r >> 6) << 6) - 44) : 0;
    const int lo1 = (i1r < SS) ? max(0, ((i1r >> 6) << 6) - 44) : 0;

    float sc[8][4];
#pragma unroll
    for (int i = 0; i < 8; i++)
#pragma unroll
        for (int k = 0; k < 4; k++) sc[i][k] = 0.f;
#pragma unroll
    for (int ks = 0; ks < 8; ks++) {
        const int col = ks*8 + t;
        unsigned a[4];
        a[0] = __float_as_uint(Qs[p0*APAD + col]);
        a[1] = __float_as_uint(Qs[p1*APAD + col]);
        a[2] = __float_as_uint(Qs[p0*APAD + col + 4]);
        a[3] = __float_as_uint(Qs[p1*APAD + col + 4]);
#pragma unroll
        for (int nf = 0; nf < 8; nf++) {
            unsigned bf[2];
            bf[0] = __float_as_uint(Ks[(nf*8+g)*APAD + col]);
            bf[1] = __float_as_uint(Ks[(nf*8+g)*APAD + col + 4]);
            mma8(sc[nf], a, bf);
        }
    }

#pragma unroll
    for (int nf = 0; nf < 8; nf++) {
#pragma unroll
        for (int ci = 0; ci < 2; ci++) {
            int jj = nf*8 + 2*t + ci;
            int j = r + STRIDE*jj;
            sc[nf][ci]     = (j < lo0) ? sc[nf][ci]     * 0.125f : -1e30f;
            sc[nf][2 + ci] = (j < lo1) ? sc[nf][2 + ci] * 0.125f : -1e30f;
        }
    }

    float mx0 = -1e30f, mx1 = -1e30f;
#pragma unroll
    for (int nf = 0; nf < 8; nf++) {
        mx0 = fmaxf(mx0, fmaxf(sc[nf][0], sc[nf][1]));
        mx1 = fmaxf(mx1, fmaxf(sc[nf][2], sc[nf][3]));
    }
    mx0 = fmaxf(mx0, __shfl_xor_sync(0xffffffffu, mx0, 1));
    mx0 = fmaxf(mx0, __shfl_xor_sync(0xffffffffu, mx0, 2));
    mx1 = fmaxf(mx1, __shfl_xor_sync(0xffffffffu, mx1, 1));
    mx1 = fmaxf(mx1, __shfl_xor_sync(0xffffffffu, mx1, 2));
    float ps0 = 0.f, ps1 = 0.f;
#pragma unroll
    for (int nf = 0; nf < 8; nf++) {
        float p0v = (sc[nf][0] > -5e29f) ? __expf(sc[nf][0] - mx0) : 0.f; sc[nf][0] = p0v; ps0 += p0v;
        float p1v = (sc[nf][1] > -5e29f) ? __expf(sc[nf][1] - mx0) : 0.f; sc[nf][1] = p1v; ps0 += p1v;
        float p2v = (sc[nf][2] > -5e29f) ? __expf(sc[nf][2] - mx1) : 0.f; sc[nf][2] = p2v; ps1 += p2v;
        float p3v = (sc[nf][3] > -5e29f) ? __expf(sc[nf][3] - mx1) : 0.f; sc[nf][3] = p3v; ps1 += p3v;
    }
    ps0 += __shfl_xor_sync(0xffffffffu, ps0, 1);
    ps0 += __shfl_xor_sync(0xffffffffu, ps0, 2);
    ps1 += __shfl_xor_sync(0xffffffffu, ps1, 1);
    ps1 += __shfl_xor_sync(0xffffffffu, ps1, 2);

    __syncthreads();    // all warps' QK^T reads of Ks done before P store
#pragma unroll
    for (int nf = 0; nf < 8; nf++) {
        Ps[p0*APAD + nf*8 + 2*t]     = rtf(sc[nf][0]);
        Ps[p0*APAD + nf*8 + 2*t + 1] = rtf(sc[nf][1]);
        Ps[p1*APAD + nf*8 + 2*t]     = rtf(sc[nf][2]);
        Ps[p1*APAD + nf*8 + 2*t + 1] = rtf(sc[nf][3]);
    }
    __syncwarp();

    float o[8][4];
#pragma unroll
    for (int i = 0; i < 8; i++)
#pragma unroll
        for (int k = 0; k < 4; k++) o[i][k] = 0.f;
#pragma unroll
    for (int ks = 0; ks < 8; ks++) {
        const int col = ks*8 + t;
        unsigned a[4];
        a[0] = __float_as_uint(Ps[p0*APAD + col]);
        a[1] = __float_as_uint(Ps[p1*APAD + col]);
        a[2] = __float_as_uint(Ps[p0*APAD + col + 4]);
        a[3] = __float_as_uint(Ps[p1*APAD + col + 4]);
#pragma unroll
        for (int nf = 0; nf < 8; nf++) {
            unsigned bf[2];
            bf[0] = __float_as_uint(Vs[col*APAD     + nf*8 + g]);
            bf[1] = __float_as_uint(Vs[(col+4)*APAD + nf*8 + g]);
            mma8(o[nf], a, bf);
        }
    }
    __syncwarp();

    const size_t rowbase = ((size_t)(b*8 + h)) * SS;
    if (i0r < SS) {
#pragma unroll
        for (int nf = 0; nf < 8; nf++) {
            int d = nf*8 + 2*t;
            *(float2*)&g_oB[(rowbase + i0r)*HD + d] = make_float2(o[nf][0], o[nf][1]);
        }
        if (t == 0) { g_mB[rowbase + i0r] = mx0; g_lB[rowbase + i0r] = ps0; }
    }
    if (i1r < SS) {
#pragma unroll
        for (int nf = 0; nf < 8; nf++) {
            int d = nf*8 + 2*t;
            *(float2*)&g_oB[(rowbase + i1r)*HD + d] = make_float2(o[nf][2], o[nf][3]);
        }
        if (t == 0) { g_mB[rowbase + i1r] = mx1; g_lB[rowbase + i1r] = ps1; }
    }
}

__device__ __forceinline__ void fixed_body(int v, float* sm)
{
    float* Qs = sm;
    float* Ks = sm + 64*APAD;
    float* Vs = sm + 2*64*APAD;
    float* Ps = Ks;                       // alias
    int* jv = (int*)(sm + 3*64*APAD);
    int* jmt = jv + 64;
    int* jdt = jmt + 64;

    const int qt = v & 31;
    const int h  = 8 + ((v >> 5) & 7);
    const int b  = v >> 8;
    const int i0 = qt * 64;

    const int nsum   = i0 / STRIDE;
    const int bstart = nsum * STRIDE;
    const int ncols  = nsum + (i0 + 64 - bstart);
    const int NT     = (ncols + 63) >> 6;

    const float* __restrict__ qb = g_q + (size_t)(b*NH + h) * SS * HD;
    const float* __restrict__ kb = g_k + (size_t)(b*NH + h) * SS * HD;
    const float* __restrict__ vb = g_v + (size_t)(b*NH + h) * SS * HD;

    const int tid = threadIdx.x;
    const int warp = tid >> 5, lane = tid & 31;
    const int g = lane >> 2, t = lane & 3;

#pragma unroll
    for (int i = 0; i < 8; i++) {
        int f = tid + i*128;
        int r = f >> 4, c4 = (f & 15) * 4;
        *(float4*)(Qs + r*APAD + c4) = *(const float4*)(qb + (size_t)(i0+r)*HD + c4);
    }

    const int r0 = i0 + warp*16 + g;
    const int r1 = r0 + 8;
    const int id0 = r0 / STRIDE, id1 = r1 / STRIDE;

    float o[8][4];
#pragma unroll
    for (int i = 0; i < 8; i++)
#pragma unroll
        for (int k = 0; k < 4; k++) o[i][k] = 0.f;
    float m0r = -1e30f, m1r = -1e30f, l0 = 0.f, l1 = 0.f;

    for (int ti = 0; ti < NT; ti++) {
        __syncthreads();
        if (tid < 64) {
            int p = ti*64 + tid;
            int j = (p < ncols) ? ((p < nsum) ? (STRIDE*p + STRIDE-1)
                                              : (bstart + p - nsum))
                                : (1 << 28);
            jv[tid] = j;
            jmt[tid] = j % STRIDE;
            jdt[tid] = j / STRIDE;
        }
#pragma unroll
        for (int i = 0; i < 8; i++) {
            int f = tid + i*128;
            int r = f >> 4, c4 = (f & 15) * 4;
            int p = ti*64 + r;
            int j = (p < ncols) ? ((p < nsum) ? (STRIDE*p + STRIDE-1)
                                              : (bstart + p - nsum)) : 0;
            *(float4*)(Ks + r*APAD + c4) = *(const float4*)(kb + (size_t)j*HD + c4);
            *(float4*)(Vs + r*APAD + c4) = *(const float4*)(vb + (size_t)j*HD + c4);
        }
        __syncthreads();

        float sc[8][4];
#pragma unroll
        for (int i = 0; i < 8; i++)
#pragma unroll
            for (int k = 0; k < 4; k++) sc[i][k] = 0.f;
        const int qr = warp*16 + g;
#pragma unroll
        for (int ks = 0; ks < 8; ks++) {
            const int col = ks*8 + t;
            unsigned a[4];
            a[0] = __float_as_uint(Qs[qr*APAD + col]);
            a[1] = __float_as_uint(Qs[(qr+8)*APAD + col]);
            a[2] = __float_as_uint(Qs[qr*APAD + col + 4]);
            a[3] = __float_as_uint(Qs[(qr+8)*APAD + col + 4]);
#pragma unroll
            for (int nf = 0; nf < 8; nf++) {
                unsigned bf[2];
                bf[0] = __float_as_uint(Ks[(nf*8+g)*APAD + col]);
                bf[1] = __float_as_uint(Ks[(nf*8+g)*APAD + col + 4]);
                mma8(sc[nf], a, bf);
            }
        }

#pragma unroll
        for (int nf = 0; nf < 8; nf++) {
#pragma unroll
            for (int ci = 0; ci < 2; ci++) {
                int jj = nf*8 + 2*t + ci;
                int j = jv[jj];
                int jmv = jmt[jj], jdv = jdt[jj];
                bool ok0 = (j <= r0) && ((jdv == id0) || (jmv >= STRIDE - SUMC));
                bool ok1 = (j <= r1) && ((jdv == id1) || (jmv >= STRIDE - SUMC));
                sc[nf][ci]     = ok0 ? sc[nf][ci]     * 0.125f : -1e30f;
                sc[nf][2 + ci] = ok1 ? sc[nf][2 + ci] * 0.125f : -1e30f;
            }
        }

        float mx0 = -1e30f, mx1 = -1e30f;
#pragma unroll
        for (int nf = 0; nf < 8; nf++) {
            mx0 = fmaxf(mx0, fmaxf(sc[nf][0], sc[nf][1]));
            mx1 = fmaxf(mx1, fmaxf(sc[nf][2], sc[nf][3]));
        }
        mx0 = fmaxf(mx0, __shfl_xor_sync(0xffffffffu, mx0, 1));
        mx0 = fmaxf(mx0, __shfl_xor_sync(0xffffffffu, mx0, 2));
        mx1 = fmaxf(mx1, __shfl_xor_sync(0xffffffffu, mx1, 1));
        mx1 = fmaxf(mx1, __shfl_xor_sync(0xffffffffu, mx1, 2));
        float nm0 = fmaxf(m0r, mx0), nm1 = fmaxf(m1r, mx1);
        float al0 = __expf(m0r - nm0), al1 = __expf(m1r - nm1);
        float ps0 = 0.f, ps1 = 0.f;
#pragma unroll
        for (int nf = 0; nf < 8; nf++) {
            float p0 = __expf(sc[nf][0] - nm0); sc[nf][0] = p0; ps0 += p0;
            float p1 = __expf(sc[nf][1] - nm0); sc[nf][1] = p1; ps0 += p1;
            float p2 = __expf(sc[nf][2] - nm1); sc[nf][2] = p2; ps1 += p2;
            float p3 = __expf(sc[nf][3] - nm1); sc[nf][3] = p3; ps1 += p3;
        }
        ps0 += __shfl_xor_sync(0xffffffffu, ps0, 1);
        ps0 += __shfl_xor_sync(0xffffffffu, ps0, 2);
        ps1 += __shfl_xor_sync(0xffffffffu, ps1, 1);
        ps1 += __shfl_xor_sync(0xffffffffu, ps1, 2);
        m0r = nm0; m1r = nm1;
        l0 = l0*al0 + ps0;
        l1 = l1*al1 + ps1;
#pragma unroll
        for (int nf = 0; nf < 8; nf++) {
            o[nf][0] *= al0; o[nf][1] *= al0;
            o[nf][2] *= al1; o[nf][3] *= al1;
        }

        __syncthreads();
#pragma unroll
        for (int nf = 0; nf < 8; nf++) {
            Ps[qr*APAD     + nf*8 + 2*t]     = rtf(sc[nf][0]);
            Ps[qr*APAD     + nf*8 + 2*t + 1] = rtf(sc[nf][1]);
            Ps[(qr+8)*APAD + nf*8 + 2*t]     = rtf(sc[nf][2]);
            Ps[(qr+8)*APAD + nf*8 + 2*t + 1] = rtf(sc[nf][3]);
        }
        __syncwarp();

#pragma unroll
        for (int ks = 0; ks < 8; ks++) {
            const int col = ks*8 + t;
            unsigned a[4];
            a[0] = __float_as_uint(Ps[qr*APAD + col]);
            a[1] = __float_as_uint(Ps[(qr+8)*APAD + col]);
            a[2] = __float_as_uint(Ps[qr*APAD + col + 4]);
            a[3] = __float_as_uint(Ps[(qr+8)*APAD + col + 4]);
#pragma unroll
            for (int nf = 0; nf < 8; nf++) {
                unsigned bf[2];
                bf[0] = __float_as_uint(Vs[col*APAD     + nf*8 + g]);
                bf[1] = __float_as_uint(Vs[(col+4)*APAD + nf*8 + g]);
                mma8(o[nf], a, bf);
            }
        }
    }

    const float inv0 = 1.f / l0, inv1 = 1.f / l1;
#pragma unroll
    for (int nf = 0; nf < 8; nf++) {
        int d = h*HD + nf*8 + 2*t;
        *(float2*)&g_o[((size_t)b*SS + r0)*HH + d] =
            make_float2(rtf(o[nf][0]*inv0), rtf(o[nf][1]*inv0));
        *(float2*)&g_o[((size_t)b*SS + r1)*HH + d] =
            make_float2(rtf(o[nf][2]*inv1), rtf(o[nf][3]*inv1));
    }
}

__global__ __launch_bounds__(128)
void attn_all()
{
    extern __shared__ float sm[];
    int bid = blockIdx.x;
    if (bid < NBLK_FIXED)                 fixed_body(bid, sm);
    else if (bid < NBLK_FIXED + NBLK_WIN) win_body(bid - NBLK_FIXED, sm);
    else                                  res_body(bid - NBLK_FIXED - NBLK_WIN, sm);
}

// ---------------------------------------------------------------------------
// Merge A + B partials for strided heads -> g_o (tf32-rounded).
// ---------------------------------------------------------------------------
__global__ __launch_bounds__(256)
void attn_merge()
{
    int idx = blockIdx.x * 256 + threadIdx.x;
    int d4 = idx & 15;
    int i  = (idx >> 4) & 2047;
    int h  = (idx >> 15) & 7;
    int b  = idx >> 18;
    size_t row = ((size_t)(b*8 + h)) * SS + i;

    float mA = g_mA[row], lA = g_lA[row];
    float mB = g_mB[row], lB = g_lB[row];
    float m = fmaxf(mA, mB);
    float eA = __expf(mA - m), eB = __expf(mB - m);
    float L = lA*eA + lB*eB;
    float inv = 1.f / L;

    float4 a = *(const float4*)&g_oA[row*HD + d4*4];
    float4 c = *(const float4*)&g_oB[row*HD + d4*4];
    float4 o;
    o.x = rtf((a.x*eA + c.x*eB) * inv);
    o.y = rtf((a.y*eA + c.y*eB) * inv);
    o.z = rtf((a.z*eA + c.z*eB) * inv);
    o.w = rtf((a.w*eA + c.w*eB) * inv);
    *(float4*)&g_o[((size_t)b*SS + i)*HH + h*HD + d4*4] = o;
}

// ---------------------------------------------------------------------------
extern "C" void kernel_launch(void* const* d_in, const int* in_sizes, int n_in,
                              void* d_out, int out_size)
{
    const float* x  = (const float*)d_in[0];
    const float* Wq = (const float*)d_in[1];
    const float* Wk = (const float*)d_in[2];
    const float* Wv = (const float*)d_in[3];
    const float* Wo = (const float*)d_in[4];
    float* out = (float*)d_out;

    cudaFuncSetAttribute(qkv_mma,   cudaFuncAttributeMaxDynamicSharedMemorySize, GEMM_SMEM2);
    cudaFuncSetAttribute(oproj_mma, cudaFuncAttributeMaxDynamicSharedMemorySize, GEMM_SMEM2);
    cudaFuncSetAttribute(attn_all,  cudaFuncAttributeMaxDynamicSharedMemorySize, ATTN_SMEM_A);

    precvt<<<(XF4 + 4*WF4 + 255)/256, 256>>>(x, Wq, Wk, Wv, Wo);
    qkv_mma<<<dim3(12, 32), 256, GEMM_SMEM2>>>();
    attn_all<<<NBLK_FIXED + NBLK_WIN + NBLK_RES, 128, ATTN_SMEM_A>>>();
    attn_merge<<<2048, 256>>>();
    oproj_mma<<<dim3(4, 32), 256, GEMM_SMEM2>>>(out);
}